// round 13
// baseline (speedup 1.0000x reference)
#include <cuda_runtime.h>
#include <math.h>
#include <stdint.h>

// Problem constants
#define BB   32        // batch
#define TT   512       // time steps
#define DD   512       // input dim
#define HH   512       // hidden dim
#define G4   2048      // 4*H
#define NLAYER 2
#define NBLK 128       // recurrent grid size

// ---------------- scratch (device globals; no allocation allowed) ----------
__device__ float d_gx[(size_t)TT * BB * G4];   // [T][B][4H] pre-activations (reused per layer)
__device__ float d_y0[(size_t)TT * BB * HH];   // [T][B][H] layer-0 outputs
__device__ float d_hbuf[2][BB * HH];           // ping-pong hidden state
__device__ unsigned int d_bar_count;           // monotonic arrival counter (zeroed by gemm)
// tf32 split operands for the input GEMMs
__device__ uint32_t d_Ahi[(size_t)TT * BB * 512];   // [16384][512]
__device__ uint32_t d_Alo[(size_t)TT * BB * 512];
__device__ uint32_t d_Whi[(size_t)G4 * 512];        // [2048][512] (current layer)
__device__ uint32_t d_Wlo[(size_t)G4 * 512];

// ---------------- tf32 helpers ----------------------------------------------
__device__ __forceinline__ uint32_t f2tf32(float a) {
    uint32_t r;
    asm("cvt.rna.tf32.f32 %0, %1;" : "=r"(r) : "f"(a));
    return r;
}

__device__ __forceinline__ void mma_tf32(float* c,
                                         uint32_t a0, uint32_t a1, uint32_t a2, uint32_t a3,
                                         uint32_t b0, uint32_t b1) {
    asm volatile("mma.sync.aligned.m16n8k8.row.col.f32.tf32.tf32.f32 "
                 "{%0,%1,%2,%3}, {%4,%5,%6,%7}, {%8,%9}, {%0,%1,%2,%3};"
                 : "+f"(c[0]), "+f"(c[1]), "+f"(c[2]), "+f"(c[3])
                 : "r"(a0), "r"(a1), "r"(a2), "r"(a3), "r"(b0), "r"(b1));
}

// ---------------- fast activations -----------------------------------------
__device__ __forceinline__ float fast_tanh(float x) {
    float y;
    asm("tanh.approx.f32 %0, %1;" : "=f"(y) : "f"(x));
    return y;
}
__device__ __forceinline__ float fast_sigmoid(float x) {
    return 0.5f + 0.5f * fast_tanh(0.5f * x);
}

// ---------------- grid-wide barrier (all blocks co-resident) ---------------
__device__ __forceinline__ void grid_barrier(unsigned int target) {
    __syncthreads();
    if (threadIdx.x == 0) {
        asm volatile("red.release.gpu.global.add.u32 [%0], 1;"
                     :: "l"(&d_bar_count) : "memory");
        unsigned int v;
        do {
            asm volatile("ld.acquire.gpu.global.u32 %0, [%1];"
                         : "=r"(v) : "l"(&d_bar_count));
        } while (v < target);
    }
    __syncthreads();
}

// ---------------- split-precision conversion kernels ------------------------
// Produce hi = tf32(v), lo = tf32(v - hi). lo*lo term (~2^-22 rel) dropped.
__global__ __launch_bounds__(256) void cvtW_kernel(const float4* __restrict__ src,
                                                   uint4* __restrict__ hi,
                                                   uint4* __restrict__ lo) {
    size_t i = (size_t)blockIdx.x * 256 + threadIdx.x;   // 262144 float4s
    float4 v = src[i];
    uint4 h, l;
    h.x = f2tf32(v.x); l.x = f2tf32(v.x - __uint_as_float(h.x));
    h.y = f2tf32(v.y); l.y = f2tf32(v.y - __uint_as_float(h.y));
    h.z = f2tf32(v.z); l.z = f2tf32(v.z - __uint_as_float(h.z));
    h.w = f2tf32(v.w); l.w = f2tf32(v.w - __uint_as_float(h.w));
    hi[i] = h; lo[i] = l;
}

// MODE 0: src = x [B][T][D] gathered to row m = t*B+b. MODE 1: src = d_y0 (already [m][k]).
template <int MODE>
__global__ __launch_bounds__(256) void cvtA_kernel(const float4* __restrict__ src,
                                                   uint4* __restrict__ hi,
                                                   uint4* __restrict__ lo) {
    size_t i = (size_t)blockIdx.x * 256 + threadIdx.x;   // 2097152 float4s
    size_t s;
    if (MODE == 0) {
        int m  = (int)(i >> 7);
        int kq = (int)(i & 127);
        int t = m >> 5, b = m & 31;
        s = ((size_t)b * TT + t) * 128 + kq;
    } else {
        s = i;
    }
    float4 v = src[s];
    uint4 h, l;
    h.x = f2tf32(v.x); l.x = f2tf32(v.x - __uint_as_float(h.x));
    h.y = f2tf32(v.y); l.y = f2tf32(v.y - __uint_as_float(h.y));
    h.z = f2tf32(v.z); l.z = f2tf32(v.z - __uint_as_float(h.z));
    h.w = f2tf32(v.w); l.w = f2tf32(v.w - __uint_as_float(h.w));
    hi[i] = h; lo[i] = l;
}

// ---------------- tf32 split GEMM: gx = A @ W^T + (bih+bhh) -----------------
// C[16384][2048], K=512. Block tile 128x64, 8 warps (4M x 2N), BK=32.
// Per warp: 32x32 out = 2 m-tiles x 4 n-tiles of m16n8k8. 3 passes/k-step.
#define GBM 128
#define GBN 64
#define GSTR 36          // row stride (32 k + 4 pad): bank = 4*row + k, conflict-free frags
#define GSM_A (GBM * GSTR)          // 4608 words per A array
#define GSM_W (GBN * GSTR)          // 2304 words per W array
#define GSM_WORDS (2 * GSM_A + 2 * GSM_W)   // 13824 words = 55296 B

__global__ __launch_bounds__(256, 2) void gemm_tf32(const float* __restrict__ bih,
                                                    const float* __restrict__ bhh) {
    extern __shared__ uint32_t smg[];
    uint32_t* sAhi = smg;
    uint32_t* sAlo = smg + GSM_A;
    uint32_t* sWhi = smg + 2 * GSM_A;
    uint32_t* sWlo = sWhi + GSM_W;

    const int tid = threadIdx.x;
    const int m0 = blockIdx.y * GBM;
    const int n0 = blockIdx.x * GBN;

    // reset the recurrent barrier counter for the following lstm_rec launch
    if (blockIdx.x == 0 && blockIdx.y == 0 && tid == 0) d_bar_count = 0u;

    const int lane = tid & 31;
    const int wid  = tid >> 5;
    const int g = lane >> 2;        // row group within tile
    const int t = lane & 3;         // thread-in-group (k / n*2 index)
    const int warpM = wid & 3;      // 0..3 -> 32 rows each
    const int warpN = wid >> 2;     // 0..1 -> 32 cols each
    const int mbase = warpM * 32;
    const int nbase = warpN * 32;

    // staging map: A: thread handles (am + it*32, kq) float4s, it=0..3; W: it=0..1
    const int am = tid >> 3;        // 0..31
    const int kq = tid & 7;         // 0..7 -> k-offset kq*4

    const uint4* gAhi = (const uint4*)d_Ahi;
    const uint4* gAlo = (const uint4*)d_Alo;
    const uint4* gWhi = (const uint4*)d_Whi;
    const uint4* gWlo = (const uint4*)d_Wlo;

    float acc[2][4][4];
#pragma unroll
    for (int mt = 0; mt < 2; ++mt)
#pragma unroll
        for (int nt = 0; nt < 4; ++nt)
#pragma unroll
            for (int r = 0; r < 4; ++r) acc[mt][nt][r] = 0.f;

    // prefetch tile 0
    uint4 rAh[4], rAl[4], rWh[2], rWl[2];
#pragma unroll
    for (int it = 0; it < 4; ++it) {
        size_t off = (size_t)(m0 + am + it * 32) * 128 + kq;
        rAh[it] = gAhi[off]; rAl[it] = gAlo[off];
    }
#pragma unroll
    for (int it = 0; it < 2; ++it) {
        size_t off = (size_t)(n0 + am + it * 32) * 128 + kq;
        rWh[it] = gWhi[off]; rWl[it] = gWlo[off];
    }

    for (int kt = 0; kt < 16; ++kt) {
        __syncthreads();
        // store staged tile
#pragma unroll
        for (int it = 0; it < 4; ++it) {
            *(uint4*)&sAhi[(am + it * 32) * GSTR + kq * 4] = rAh[it];
            *(uint4*)&sAlo[(am + it * 32) * GSTR + kq * 4] = rAl[it];
        }
#pragma unroll
        for (int it = 0; it < 2; ++it) {
            *(uint4*)&sWhi[(am + it * 32) * GSTR + kq * 4] = rWh[it];
            *(uint4*)&sWlo[(am + it * 32) * GSTR + kq * 4] = rWl[it];
        }
        __syncthreads();
        // prefetch next tile
        if (kt < 15) {
            const int kn = (kt + 1) * 8 + kq;
#pragma unroll
            for (int it = 0; it < 4; ++it) {
                size_t off = (size_t)(m0 + am + it * 32) * 128 + kn;
                rAh[it] = gAhi[off]; rAl[it] = gAlo[off];
            }
#pragma unroll
            for (int it = 0; it < 2; ++it) {
                size_t off = (size_t)(n0 + am + it * 32) * 128 + kn;
                rWh[it] = gWhi[off]; rWl[it] = gWlo[off];
            }
        }
        // compute 4 k8-steps
#pragma unroll
        for (int ks = 0; ks < 4; ++ks) {
            const int kb = ks * 8 + t;
            // W fragments for all 4 n-tiles (hi+lo)
            uint32_t wh[4][2], wl[4][2];
#pragma unroll
            for (int nt = 0; nt < 4; ++nt) {
                const int q = (nbase + nt * 8 + g) * GSTR + kb;
                wh[nt][0] = sWhi[q]; wh[nt][1] = sWhi[q + 4];
                wl[nt][0] = sWlo[q]; wl[nt][1] = sWlo[q + 4];
            }
#pragma unroll
            for (int mt = 0; mt < 2; ++mt) {
                const int r  = (mbase + mt * 16 + g) * GSTR + kb;
                const int r8 = r + 8 * GSTR;
                uint32_t a0 = sAhi[r],  a1 = sAhi[r8],  a2 = sAhi[r + 4],  a3 = sAhi[r8 + 4];
                uint32_t l0 = sAlo[r],  l1 = sAlo[r8],  l2 = sAlo[r + 4],  l3 = sAlo[r8 + 4];
#pragma unroll
                for (int nt = 0; nt < 4; ++nt) {
                    mma_tf32(acc[mt][nt], a0, a1, a2, a3, wh[nt][0], wh[nt][1]);
                    mma_tf32(acc[mt][nt], a0, a1, a2, a3, wl[nt][0], wl[nt][1]);
                    mma_tf32(acc[mt][nt], l0, l1, l2, l3, wh[nt][0], wh[nt][1]);
                }
            }
        }
    }

    // epilogue: bias + store
#pragma unroll
    for (int nt = 0; nt < 4; ++nt) {
        const int col = n0 + nbase + nt * 8 + 2 * t;
        const float b0 = bih[col] + bhh[col];
        const float b1 = bih[col + 1] + bhh[col + 1];
#pragma unroll
        for (int mt = 0; mt < 2; ++mt) {
            const int row = m0 + mbase + mt * 16 + g;
            float2 v0 = make_float2(acc[mt][nt][0] + b0, acc[mt][nt][1] + b1);
            float2 v1 = make_float2(acc[mt][nt][2] + b0, acc[mt][nt][3] + b1);
            *(float2*)&d_gx[(size_t)row * G4 + col]       = v0;
            *(float2*)&d_gx[(size_t)(row + 8) * G4 + col] = v1;
        }
    }
}

// ---------------- persistent recurrent kernel (unchanged from R12) ----------
#define PSTRIDE 17
#define SMEM_W   (16 * 512)           // 8192 floats
#define SMEM_H   (32 * 516)           // padded h, 16512 floats
#define SMEM_P   (4 * 32 * PSTRIDE)   // 2176 floats
#define SMEM_REC_FLOATS (SMEM_W + SMEM_H + SMEM_P)
#define SMEM_REC_BYTES  (SMEM_REC_FLOATS * 4)

__global__ void lstm_rec(const float* __restrict__ Whh,   // layer's [2048][512]
                         int store_y,
                         float* __restrict__ out_h,       // [B][H] slice of d_out
                         float* __restrict__ out_c) {
    extern __shared__ float sm[];
    float* Wsh = sm;                    // [16][512]
    float* hsh = sm + SMEM_W;           // [32][516]
    float* psh = hsh + SMEM_H;          // [4][32][17]

    const int tid  = threadIdx.x;
    const int warp = tid >> 5;
    const int lane = tid & 31;
    const int hidx0 = blockIdx.x * 4;

    for (int idx = tid; idx < 16 * 512; idx += 256) {
        int j = idx >> 9, k = idx & 511;
        int gate = j & 3, hl = j >> 2;
        Wsh[idx] = Whh[(size_t)(gate * HH + hidx0 + hl) * HH + k];
    }

    const int rg = warp & 1;        // row group (rows rg*8 .. rg*8+7)
    const int ks = warp >> 1;       // k-split 0..3
    const int kbase = ks * 128;

    float c_reg = 0.f;              // cell state (threads 0..127)
    const int ab  = tid >> 2;       // batch for activation
    const int ahl = tid & 3;        // local hidden unit for activation
    const int hid = hidx0 + ahl;
    const float* gxbase = d_gx + (size_t)ab * G4 + hid;

    __syncthreads();

    for (int t = 0; t < TT; ++t) {
        float gxi, gxf, gxg, gxo;
        if (tid < 128) {
            const float* gxp = gxbase + (size_t)t * (BB * G4);
            gxi = __ldcs(gxp + 0 * HH);
            gxf = __ldcs(gxp + 1 * HH);
            gxg = __ldcs(gxp + 2 * HH);
            gxo = __ldcs(gxp + 3 * HH);
        }

        if (t == 0) {
            for (int i = tid; i < SMEM_H; i += 256) hsh[i] = 0.f;
        } else {
            const float4* hb = (const float4*)&d_hbuf[t & 1][0];
            for (int i = tid; i < 4096; i += 256) {
                float4 v = __ldcg(hb + i);
                *(float4*)&hsh[(i >> 7) * 516 + (i & 127) * 4] = v;
            }
        }
        __syncthreads();

        float acc[8];
#pragma unroll
        for (int r = 0; r < 8; ++r) acc[r] = 0.f;
        const float4* hrow = (const float4*)&hsh[lane * 516 + kbase];
#pragma unroll 4
        for (int kk = 0; kk < 32; ++kk) {
            const float4 hv = hrow[kk];
#pragma unroll
            for (int r = 0; r < 8; ++r) {
                const float4 wv = *(const float4*)&Wsh[(rg * 8 + r) * 512 + kbase + kk * 4];
                acc[r] = fmaf(hv.x, wv.x, acc[r]);
                acc[r] = fmaf(hv.y, wv.y, acc[r]);
                acc[r] = fmaf(hv.z, wv.z, acc[r]);
                acc[r] = fmaf(hv.w, wv.w, acc[r]);
            }
        }
        float* pw = &psh[ks * (32 * PSTRIDE) + lane * PSTRIDE + rg * 8];
#pragma unroll
        for (int r = 0; r < 8; ++r) pw[r] = acc[r];
        __syncthreads();

        if (tid < 128) {
            const float* pr = &psh[ab * PSTRIDE + ahl * 4];
            float pi = 0.f, pf = 0.f, pg = 0.f, po = 0.f;
#pragma unroll
            for (int q = 0; q < 4; ++q) {
                const float* p = pr + q * (32 * PSTRIDE);
                pi += p[0]; pf += p[1]; pg += p[2]; po += p[3];
            }
            pi += gxi; pf += gxf; pg += gxg; po += gxo;
            const float ig = fast_sigmoid(pi);
            const float fg = fast_sigmoid(pf);
            const float gg = fast_tanh(pg);
            const float og = fast_sigmoid(po);
            c_reg = fg * c_reg + ig * gg;
            const float h = og * fast_tanh(c_reg);
            __stcg(&d_hbuf[(t + 1) & 1][ab * HH + hid], h);
            if (store_y) __stcs(&d_y0[((size_t)t * BB + ab) * HH + hid], h);
            if (t == TT - 1) {
                out_h[ab * HH + hid] = h;
                out_c[ab * HH + hid] = c_reg;
            }
        }
        if (t != TT - 1) grid_barrier((unsigned int)(t + 1) * NBLK);
    }
}

// ---------------- launch ----------------------------------------------------
extern "C" void kernel_launch(void* const* d_in, const int* in_sizes, int n_in,
                              void* d_out, int out_size) {
    (void)in_sizes; (void)n_in; (void)out_size;
    const float* x    = (const float*)d_in[0];   // [32][512][512]
    const float* W_ih = (const float*)d_in[1];   // [2][2048][512]
    const float* W_hh = (const float*)d_in[2];   // [2][2048][512]
    const float* b_ih = (const float*)d_in[3];   // [2][2048]
    const float* b_hh = (const float*)d_in[4];   // [2][2048]
    float* out = (float*)d_out;                  // h_n [2][32][512] then c_n [2][32][512]

    cudaFuncSetAttribute(lstm_rec, cudaFuncAttributeMaxDynamicSharedMemorySize,
                         SMEM_REC_BYTES);
    cudaFuncSetAttribute(gemm_tf32, cudaFuncAttributeMaxDynamicSharedMemorySize,
                         GSM_WORDS * 4);

    uint4* Ahi4 = nullptr; uint4* Alo4 = nullptr;
    uint4* Whi4 = nullptr; uint4* Wlo4 = nullptr;
    cudaGetSymbolAddress((void**)&Ahi4, d_Ahi);
    cudaGetSymbolAddress((void**)&Alo4, d_Alo);
    cudaGetSymbolAddress((void**)&Whi4, d_Whi);
    cudaGetSymbolAddress((void**)&Wlo4, d_Wlo);
    float* y0p = nullptr;
    cudaGetSymbolAddress((void**)&y0p, d_y0);

    const dim3 ggrid(G4 / GBN, (TT * BB) / GBM);   // (32, 128)
    const size_t wstride = (size_t)G4 * HH;        // per-layer weight stride
    const int LBH = NLAYER * BB * HH;              // 32768: offset of c_n block

    // ---- layer 0 ----
    cvtW_kernel<<<1024, 256>>>((const float4*)W_ih, Whi4, Wlo4);
    cvtA_kernel<0><<<8192, 256>>>((const float4*)x, Ahi4, Alo4);
    gemm_tf32<<<ggrid, 256, GSM_WORDS * 4>>>(b_ih, b_hh);
    lstm_rec<<<NBLK, 256, SMEM_REC_BYTES>>>(W_hh, 1,
                                            out + 0 * BB * HH,
                                            out + LBH + 0 * BB * HH);
    // ---- layer 1 ----
    cvtW_kernel<<<1024, 256>>>((const float4*)(W_ih + wstride), Whi4, Wlo4);
    cvtA_kernel<1><<<8192, 256>>>((const float4*)y0p, Ahi4, Alo4);
    gemm_tf32<<<ggrid, 256, GSM_WORDS * 4>>>(b_ih + G4, b_hh + G4);
    lstm_rec<<<NBLK, 256, SMEM_REC_BYTES>>>(W_hh + wstride, 0,
                                            out + 1 * BB * HH,
                                            out + LBH + 1 * BB * HH);
}

// round 16
// speedup vs baseline: 1.1251x; 1.1251x over previous
#include <cuda_runtime.h>
#include <math.h>

// Problem constants
#define BB   32        // batch
#define TT   512       // time steps
#define DD   512       // input dim
#define HH   512       // hidden dim
#define G4   2048      // 4*H
#define NLAYER 2
#define NBLK 128       // recurrent grid size

// ---------------- scratch (device globals; no allocation allowed) ----------
__device__ float d_gx[(size_t)TT * BB * G4];   // [T][B][4H] pre-activations (reused per layer)
__device__ float d_y0[(size_t)TT * BB * HH];   // [T][B][H] layer-0 outputs
__device__ float d_hbuf[2][BB * HH];           // ping-pong hidden state
__device__ unsigned int d_bar_count;           // monotonic arrival counter (zeroed by gemm)

// ---------------- fast activations -----------------------------------------
__device__ __forceinline__ float fast_tanh(float x) {
    float y;
    asm("tanh.approx.f32 %0, %1;" : "=f"(y) : "f"(x));
    return y;
}
__device__ __forceinline__ float fast_sigmoid(float x) {
    return 0.5f + 0.5f * fast_tanh(0.5f * x);
}

// ---------------- grid-wide barrier (all blocks co-resident) ---------------
// Monotonic counter: arrival = red.release (no-return REDG), wait = spin on
// ld.acquire until count >= iter*NBLK. Counter is zeroed by the preceding
// gemm launch (stream order). 128 blocks, 1 block/SM (smem+regs) on 148 SMs:
// wave-1 residency guaranteed -> deadlock-free.
__device__ __forceinline__ void grid_barrier(unsigned int target) {
    __syncthreads();
    if (threadIdx.x == 0) {
        asm volatile("red.release.gpu.global.add.u32 [%0], 1;"
                     :: "l"(&d_bar_count) : "memory");
        unsigned int v;
        do {
            asm volatile("ld.acquire.gpu.global.u32 %0, [%1];"
                         : "=r"(v) : "l"(&d_bar_count));
        } while (v < target);
    }
    __syncthreads();
}

// ---------------- big GEMM: gx = A @ Wih^T + (bih+bhh) ---------------------
// M=16384 (rows m = t*B + b), N=2048, K=512.  (R4/R12 scalar-FFMA version)
// MODE 0: A = x [B][T][D] (row offset (b*T+t)*D). MODE 1: A = d_y0 (offset m*H).
template <int MODE>
__global__ __launch_bounds__(256) void gemm_gx(const float* __restrict__ A,
                                               const float* __restrict__ W,
                                               const float* __restrict__ bih,
                                               const float* __restrict__ bhh) {
    __shared__ float As[8][132];
    __shared__ float Bs[8][132];

    const int tid = threadIdx.x;
    const int m0 = blockIdx.y * 128;
    const int n0 = blockIdx.x * 128;

    // reset the recurrent barrier counter for the following lstm_rec launch
    if (blockIdx.x == 0 && blockIdx.y == 0 && tid == 0) d_bar_count = 0u;

    const int lr = tid >> 1;         // 0..127: row within tile
    const int lk = (tid & 1) * 4;    // 0 or 4: k offset within 8-wide tile

    const float* Abase = (MODE == 0) ? A : d_y0;
    size_t aoff;
    {
        int m = m0 + lr;
        if (MODE == 0) {
            int t = m >> 5;          // m / 32  (B == 32)
            int b = m & 31;
            aoff = ((size_t)b * TT + t) * DD;
        } else {
            aoff = (size_t)m * HH;
        }
    }
    const float4* Aload = (const float4*)(Abase + aoff);
    const float4* Wload = (const float4*)(W + (size_t)(n0 + lr) * 512);

    const int tx = tid & 15;
    const int ty = tid >> 4;

    float acc[8][8];
#pragma unroll
    for (int i = 0; i < 8; ++i)
#pragma unroll
        for (int j = 0; j < 8; ++j) acc[i][j] = 0.f;

    // prefetch tile 0
    float4 ar = Aload[lk >> 2];
    float4 wr = Wload[lk >> 2];

    for (int kt = 0; kt < 64; ++kt) {
        __syncthreads();
        As[lk + 0][lr] = ar.x; As[lk + 1][lr] = ar.y;
        As[lk + 2][lr] = ar.z; As[lk + 3][lr] = ar.w;
        Bs[lk + 0][lr] = wr.x; Bs[lk + 1][lr] = wr.y;
        Bs[lk + 2][lr] = wr.z; Bs[lk + 3][lr] = wr.w;
        __syncthreads();
        if (kt < 63) {   // prefetch next tile while computing this one
            ar = Aload[(kt + 1) * 2 + (lk >> 2)];
            wr = Wload[(kt + 1) * 2 + (lk >> 2)];
        }
#pragma unroll
        for (int k = 0; k < 8; ++k) {
            const float4 a0 = *(const float4*)(&As[k][ty * 4]);
            const float4 a1 = *(const float4*)(&As[k][64 + ty * 4]);
            const float4 b0 = *(const float4*)(&Bs[k][tx * 4]);
            const float4 b1 = *(const float4*)(&Bs[k][64 + tx * 4]);
            const float av[8] = {a0.x, a0.y, a0.z, a0.w, a1.x, a1.y, a1.z, a1.w};
            const float bv[8] = {b0.x, b0.y, b0.z, b0.w, b1.x, b1.y, b1.z, b1.w};
#pragma unroll
            for (int i = 0; i < 8; ++i)
#pragma unroll
                for (int j = 0; j < 8; ++j)
                    acc[i][j] = fmaf(av[i], bv[j], acc[i][j]);
        }
    }

    // bias + store
    float bias[8];
#pragma unroll
    for (int j = 0; j < 8; ++j) {
        int nn = n0 + ((j < 4) ? (tx * 4 + j) : (64 + tx * 4 + j - 4));
        bias[j] = bih[nn] + bhh[nn];
    }
#pragma unroll
    for (int i = 0; i < 8; ++i) {
        int mrow = m0 + ((i < 4) ? (ty * 4 + i) : (64 + ty * 4 + i - 4));
        float4 o0, o1;
        o0.x = acc[i][0] + bias[0]; o0.y = acc[i][1] + bias[1];
        o0.z = acc[i][2] + bias[2]; o0.w = acc[i][3] + bias[3];
        o1.x = acc[i][4] + bias[4]; o1.y = acc[i][5] + bias[5];
        o1.z = acc[i][6] + bias[6]; o1.w = acc[i][7] + bias[7];
        *(float4*)&d_gx[(size_t)mrow * G4 + n0 + tx * 4]      = o0;
        *(float4*)&d_gx[(size_t)mrow * G4 + n0 + 64 + tx * 4] = o1;
    }
}

// ---------------- persistent recurrent kernel (512 threads) -----------------
// 128 blocks x 512 threads (16 warps, 4/SMSP for latency hiding; regs uncapped
// via __launch_bounds__(512,1) -> up to 128/thread for deep LDS->FFMA pipelining).
// Block owns hidden units [blockIdx.x*4, +4) => 16 Whh rows in shared for all
// 512 steps. Warp w: row-group rg=w&1 (8 rows), k-split ks=w>>1 (8 splits x 64 k).
// lane = batch. Activation: threads 0..127, one (batch, unit) each.
#define NTH 512
#define PSTRIDE 17
#define SMEM_W   (16 * 512)           // 8192 floats
#define SMEM_H   (32 * 516)           // padded h, 16512 floats
#define SMEM_P   (8 * 32 * PSTRIDE)   // 4352 floats
#define SMEM_REC_FLOATS (SMEM_W + SMEM_H + SMEM_P)
#define SMEM_REC_BYTES  (SMEM_REC_FLOATS * 4)      // ~116 KB

__global__ __launch_bounds__(NTH, 1)
void lstm_rec(const float* __restrict__ Whh,   // layer's [2048][512]
              int store_y,
              float* __restrict__ out_h,       // [B][H] slice of d_out
              float* __restrict__ out_c) {
    extern __shared__ float sm[];
    float* Wsh = sm;                    // [16][512]
    float* hsh = sm + SMEM_W;           // [32][516]
    float* psh = hsh + SMEM_H;          // [8][32][17]

    const int tid  = threadIdx.x;
    const int warp = tid >> 5;
    const int lane = tid & 31;
    const int hidx0 = blockIdx.x * 4;

    // load the 16 Whh rows this block owns (reused for all 512 steps)
    for (int idx = tid; idx < 16 * 512; idx += NTH) {
        int j = idx >> 9, k = idx & 511;
        int gate = j & 3, hl = j >> 2;
        Wsh[idx] = Whh[(size_t)(gate * HH + hidx0 + hl) * HH + k];
    }

    const int rg = warp & 1;        // row group (rows rg*8 .. rg*8+7)
    const int ks = warp >> 1;       // k-split 0..7 (64 k each)
    const int kbase = ks * 64;

    float c_reg = 0.f;              // cell state (threads 0..127)
    const int ab  = tid >> 2;       // batch for activation
    const int ahl = tid & 3;        // local hidden unit for activation
    const int hid = hidx0 + ahl;
    const float* gxbase = d_gx + (size_t)ab * G4 + hid;   // advance by B*G4 per t

    __syncthreads();

    for (int t = 0; t < TT; ++t) {
        // ---- prefetch gate pre-activations (independent of h; latency
        //      hidden under h-staging + dot-product loop) ----
        float gxi, gxf, gxg, gxo;
        if (tid < 128) {
            const float* gxp = gxbase + (size_t)t * (BB * G4);
            gxi = __ldcs(gxp + 0 * HH);
            gxf = __ldcs(gxp + 1 * HH);
            gxg = __ldcs(gxp + 2 * HH);
            gxo = __ldcs(gxp + 3 * HH);
        }

        // ---- stage h_t into shared ----
        if (t == 0) {
            for (int i = tid; i < SMEM_H; i += NTH) hsh[i] = 0.f;
        } else {
            const float4* hb = (const float4*)&d_hbuf[t & 1][0];
            for (int i = tid; i < 4096; i += NTH) {
                float4 v = __ldcg(hb + i);                       // bypass stale L1
                *(float4*)&hsh[(i >> 7) * 516 + (i & 127) * 4] = v;
            }
        }
        __syncthreads();

        // ---- dot products: acc[r] = sum_{k in 64-chunk} Wsh[rg*8+r][k]*h[lane][k]
        float acc[8];
#pragma unroll
        for (int r = 0; r < 8; ++r) acc[r] = 0.f;
        const float4* hrow = (const float4*)&hsh[lane * 516 + kbase];
#pragma unroll
        for (int kk = 0; kk < 16; ++kk) {
            const float4 hv = hrow[kk];
#pragma unroll
            for (int r = 0; r < 8; ++r) {
                const float4 wv = *(const float4*)&Wsh[(rg * 8 + r) * 512 + kbase + kk * 4];
                acc[r] = fmaf(hv.x, wv.x, acc[r]);
                acc[r] = fmaf(hv.y, wv.y, acc[r]);
                acc[r] = fmaf(hv.z, wv.z, acc[r]);
                acc[r] = fmaf(hv.w, wv.w, acc[r]);
            }
        }
        // conflict-free partial-sum writes: lane stride 17 (odd)
        float* pw = &psh[ks * (32 * PSTRIDE) + lane * PSTRIDE + rg * 8];
#pragma unroll
        for (int r = 0; r < 8; ++r) pw[r] = acc[r];
        __syncthreads();

        // ---- activation (threads 0..127: one (batch, unit) each) ----
        if (tid < 128) {
            const float* pr = &psh[ab * PSTRIDE + ahl * 4];
            float pi = 0.f, pf = 0.f, pg = 0.f, po = 0.f;
#pragma unroll
            for (int q = 0; q < 8; ++q) {
                const float* p = pr + q * (32 * PSTRIDE);
                pi += p[0]; pf += p[1]; pg += p[2]; po += p[3];
            }
            pi += gxi; pf += gxf; pg += gxg; po += gxo;
            const float ig = fast_sigmoid(pi);
            const float fg = fast_sigmoid(pf);
            const float gg = fast_tanh(pg);
            const float og = fast_sigmoid(po);
            c_reg = fg * c_reg + ig * gg;
            const float h = og * fast_tanh(c_reg);
            __stcg(&d_hbuf[(t + 1) & 1][ab * HH + hid], h);
            if (store_y) __stcs(&d_y0[((size_t)t * BB + ab) * HH + hid], h);
            if (t == TT - 1) {
                out_h[ab * HH + hid] = h;
                out_c[ab * HH + hid] = c_reg;
            }
        }
        if (t != TT - 1) grid_barrier((unsigned int)(t + 1) * NBLK);
    }
}

// ---------------- launch ----------------------------------------------------
extern "C" void kernel_launch(void* const* d_in, const int* in_sizes, int n_in,
                              void* d_out, int out_size) {
    (void)in_sizes; (void)n_in; (void)out_size;
    const float* x    = (const float*)d_in[0];   // [32][512][512]
    const float* W_ih = (const float*)d_in[1];   // [2][2048][512]
    const float* W_hh = (const float*)d_in[2];   // [2][2048][512]
    const float* b_ih = (const float*)d_in[3];   // [2][2048]
    const float* b_hh = (const float*)d_in[4];   // [2][2048]
    float* out = (float*)d_out;                  // h_n [2][32][512] then c_n [2][32][512]

    cudaFuncSetAttribute(lstm_rec, cudaFuncAttributeMaxDynamicSharedMemorySize,
                         SMEM_REC_BYTES);

    const dim3 ggrid(16, 128);   // N tiles x M tiles
    const size_t wstride = (size_t)G4 * HH;      // per-layer weight stride
    const int LBH = NLAYER * BB * HH;            // 32768: offset of c_n block

    // layer 0
    gemm_gx<0><<<ggrid, 256>>>(x, W_ih, b_ih, b_hh);
    lstm_rec<<<NBLK, NTH, SMEM_REC_BYTES>>>(W_hh, 1,
                                            out + 0 * BB * HH,
                                            out + LBH + 0 * BB * HH);
    // layer 1 (input = d_y0, consumed inside gemm_gx<1>)
    gemm_gx<1><<<ggrid, 256>>>(nullptr, W_ih + wstride, b_ih + G4, b_hh + G4);
    lstm_rec<<<NBLK, NTH, SMEM_REC_BYTES>>>(W_hh + wstride, 0,
                                            out + 1 * BB * HH,
                                            out + LBH + 1 * BB * HH);
}